// round 2
// baseline (speedup 1.0000x reference)
#include <cuda_runtime.h>
#include <cuda_bf16.h>
#include <math.h>

// Problem constants
#define NOBS   8192
#define NTOP   128
#define NDIM   64
#define NBATCH 8192

// Scratch (no cudaMalloc allowed)
__device__ float  g_X[NOBS * NDIM];   // embedded points
__device__ float  g_sq[NOBS];         // row squared norms
__device__ double g_part;             // global partition sum

__device__ __forceinline__ float gumbel_of(float u) {
    // g = -log(-log(u+eps)+eps), eps = 1e-9 (precise logf: sensitive near u->1)
    return -logf(-logf(u + 1e-9f) + 1e-9f);
}

// Warp-cooperative gumbel softmax over 128 topics; lane owns topics {lane, lane+32, lane+64, lane+96}
__device__ __forceinline__ void gumbel_softmax4(const float* __restrict__ lrow,
                                                const float* __restrict__ nrow,
                                                int lane, float z[4]) {
    float m = -1e30f;
#pragma unroll
    for (int c = 0; c < 4; c++) {
        int t = lane + 32 * c;
        z[c] = lrow[t] + gumbel_of(nrow[t]);
        m = fmaxf(m, z[c]);
    }
#pragma unroll
    for (int o = 16; o > 0; o >>= 1) m = fmaxf(m, __shfl_xor_sync(0xffffffffu, m, o));
    float s = 0.f;
#pragma unroll
    for (int c = 0; c < 4; c++) { z[c] = expf(z[c] - m); s += z[c]; }
#pragma unroll
    for (int o = 16; o > 0; o >>= 1) s += __shfl_xor_sync(0xffffffffu, s, o);
    float inv = 1.f / s;
#pragma unroll
    for (int c = 0; c < 4; c++) z[c] *= inv;
}

__global__ void k_zero() { g_part = 0.0; }

// ---------------------------------------------------------------------------
// K1: x = softmax(logits + g) @ W^T + b ; also row squared norms.
// 256 threads = 8 warps; each warp does 4 rows; W cached in smem (padded 129
// stride so lanes with distinct d hit distinct banks).
// ---------------------------------------------------------------------------
__global__ void __launch_bounds__(256) k_embed(const float* __restrict__ logits,
                                               const float* __restrict__ noise,
                                               const float* __restrict__ W,
                                               const float* __restrict__ bias) {
    __shared__ float Wsm[NDIM * 129];
    __shared__ float zsm[8 * NTOP];
    int tid = threadIdx.x, w = tid >> 5, lane = tid & 31;

    for (int idx = tid; idx < NDIM * NTOP; idx += 256)
        Wsm[(idx >> 7) * 129 + (idx & 127)] = W[idx];
    __syncthreads();

    for (int r = 0; r < 4; r++) {
        int row = blockIdx.x * 32 + w * 4 + r;
        float z[4];
        gumbel_softmax4(logits + (size_t)row * NTOP, noise + (size_t)row * NTOP, lane, z);
#pragma unroll
        for (int c = 0; c < 4; c++) zsm[w * NTOP + lane + 32 * c] = z[c];
        __syncwarp();

        float acc = 0.f;
#pragma unroll
        for (int h = 0; h < 2; h++) {
            int d = lane + 32 * h;
            float xd = bias[d];
            const float* zp = &zsm[w * NTOP];
            const float* wp = &Wsm[d * 129];
#pragma unroll 8
            for (int t = 0; t < NTOP; t++) xd = fmaf(zp[t], wp[t], xd);
            g_X[(size_t)row * NDIM + d] = xd;
            acc = fmaf(xd, xd, acc);
        }
#pragma unroll
        for (int o = 16; o > 0; o >>= 1) acc += __shfl_xor_sync(0xffffffffu, acc, o);
        if (lane == 0) g_sq[row] = acc;
        __syncwarp();
    }
}

// ---------------------------------------------------------------------------
// K2: part = sum_{i != j} 1/(1 + ||x_i - x_j||^2), symmetric -> only bi <= bj
// tiles. 128x128 tile per block, 16x16 threads x (8x8 per thread), k-major
// smem tiles so the inner loop is pure float4 LDS + FFMA.
// ---------------------------------------------------------------------------
__global__ void __launch_bounds__(256) k_pairwise() {
    int bj = blockIdx.x, bi = blockIdx.y;
    if (bi > bj) return;

    extern __shared__ float sm[];
    float* As = sm;                 // [64][128] k-major
    float* Bs = sm + NDIM * 128;    // [64][128] k-major
    int tid = threadIdx.x;

    {   // cooperative transpose-load of both tiles (coalesced float4 reads)
        int m  = tid >> 1;
        int kh = (tid & 1) << 5;    // 0 or 32
        const float4* pa = reinterpret_cast<const float4*>(&g_X[((size_t)bi * 128 + m) * NDIM + kh]);
        const float4* pb = reinterpret_cast<const float4*>(&g_X[((size_t)bj * 128 + m) * NDIM + kh]);
#pragma unroll
        for (int q = 0; q < 8; q++) {
            float4 va = pa[q], vb = pb[q];
            int k = kh + q * 4;
            As[(k + 0) * 128 + m] = va.x; As[(k + 1) * 128 + m] = va.y;
            As[(k + 2) * 128 + m] = va.z; As[(k + 3) * 128 + m] = va.w;
            Bs[(k + 0) * 128 + m] = vb.x; Bs[(k + 1) * 128 + m] = vb.y;
            Bs[(k + 2) * 128 + m] = vb.z; Bs[(k + 3) * 128 + m] = vb.w;
        }
    }
    __syncthreads();

    int tx = tid & 15, ty = tid >> 4;
    float c[8][8];
#pragma unroll
    for (int m = 0; m < 8; m++)
#pragma unroll
        for (int n = 0; n < 8; n++) c[m][n] = 0.f;

#pragma unroll 4
    for (int k = 0; k < NDIM; k++) {
        float4 a0 = *reinterpret_cast<float4*>(&As[k * 128 + ty * 8]);
        float4 a1 = *reinterpret_cast<float4*>(&As[k * 128 + ty * 8 + 4]);
        float4 b0 = *reinterpret_cast<float4*>(&Bs[k * 128 + tx * 8]);
        float4 b1 = *reinterpret_cast<float4*>(&Bs[k * 128 + tx * 8 + 4]);
        float a[8] = {a0.x, a0.y, a0.z, a0.w, a1.x, a1.y, a1.z, a1.w};
        float b[8] = {b0.x, b0.y, b0.z, b0.w, b1.x, b1.y, b1.z, b1.w};
#pragma unroll
        for (int m = 0; m < 8; m++)
#pragma unroll
            for (int n = 0; n < 8; n++) c[m][n] = fmaf(a[m], b[n], c[m][n]);
    }

    float sa[8], sb[8];
#pragma unroll
    for (int m = 0; m < 8; m++) sa[m] = g_sq[bi * 128 + ty * 8 + m];
#pragma unroll
    for (int n = 0; n < 8; n++) sb[n] = g_sq[bj * 128 + tx * 8 + n];

    bool diag = (bi == bj);
    float acc = 0.f;
#pragma unroll
    for (int m = 0; m < 8; m++) {
#pragma unroll
        for (int n = 0; n < 8; n++) {
            float d = sa[m] + sb[n] - 2.f * c[m][n];
            float v = __fdividef(1.f, 1.f + d);
            if (!(diag && (ty * 8 + m) == (tx * 8 + n))) acc += v;
        }
    }

#pragma unroll
    for (int o = 16; o > 0; o >>= 1) acc += __shfl_xor_sync(0xffffffffu, acc, o);
    __shared__ float red[8];
    int lane = tid & 31, w = tid >> 5;
    if (lane == 0) red[w] = acc;
    __syncthreads();
    if (tid == 0) {
        float s = 0.f;
#pragma unroll
        for (int q = 0; q < 8; q++) s += red[q];
        atomicAdd(&g_part, (double)s * (diag ? 1.0 : 2.0));
    }
}

// ---------------------------------------------------------------------------
// K3: per-batch loss. xi - xj = (zi - zj) @ W^T  (bias cancels).
// den = 64 + ||xi-xj||^2 ; loss = pij*(log pij + log den + log part)
// ---------------------------------------------------------------------------
__global__ void __launch_bounds__(256) k_loss(const float* __restrict__ pij,
                                              const float* __restrict__ noise_i,
                                              const float* __restrict__ noise_j,
                                              const float* __restrict__ logits,
                                              const float* __restrict__ W,
                                              const int* __restrict__ iv,
                                              const int* __restrict__ jv,
                                              float* __restrict__ out) {
    __shared__ float Wsm[NDIM * 129];
    __shared__ float zsm[8 * NTOP];
    int tid = threadIdx.x, w = tid >> 5, lane = tid & 31;

    for (int idx = tid; idx < NDIM * NTOP; idx += 256)
        Wsm[(idx >> 7) * 129 + (idx & 127)] = W[idx];
    __syncthreads();

    for (int e = 0; e < 4; e++) {
        int el = blockIdx.x * 32 + w * 4 + e;
        int ri = iv[el], rj = jv[el];
        float zi[4], zj[4];
        gumbel_softmax4(logits + (size_t)ri * NTOP, noise_i + (size_t)el * NTOP, lane, zi);
        gumbel_softmax4(logits + (size_t)rj * NTOP, noise_j + (size_t)el * NTOP, lane, zj);
#pragma unroll
        for (int c = 0; c < 4; c++) zsm[w * NTOP + lane + 32 * c] = zi[c] - zj[c];
        __syncwarp();

        float acc = 0.f;
#pragma unroll
        for (int h = 0; h < 2; h++) {
            int d = lane + 32 * h;
            float xd = 0.f;
            const float* zp = &zsm[w * NTOP];
            const float* wp = &Wsm[d * 129];
#pragma unroll 8
            for (int t = 0; t < NTOP; t++) xd = fmaf(zp[t], wp[t], xd);
            acc = fmaf(xd, xd, acc);
        }
#pragma unroll
        for (int o = 16; o > 0; o >>= 1) acc += __shfl_xor_sync(0xffffffffu, acc, o);

        if (lane == 0) {
            float den = (float)NDIM + acc;
            float p = pij[el];
            float lp = logf((float)g_part);
            out[el] = p * (logf(p) + logf(den) + lp);
        }
        __syncwarp();
    }
}

extern "C" void kernel_launch(void* const* d_in, const int* in_sizes, int n_in,
                              void* d_out, int out_size) {
    const float* pij        = (const float*)d_in[0];
    const float* noise_full = (const float*)d_in[1];
    const float* noise_i    = (const float*)d_in[2];
    const float* noise_j    = (const float*)d_in[3];
    const float* logits     = (const float*)d_in[4];
    const float* W          = (const float*)d_in[5];
    const float* bias       = (const float*)d_in[6];
    const int*   iv         = (const int*)d_in[7];
    const int*   jv         = (const int*)d_in[8];
    float* out = (float*)d_out;

    // 64KB dynamic smem for the pairwise tile kernel (idempotent, host-side,
    // not a stream op -> graph-capture safe)
    cudaFuncSetAttribute(k_pairwise, cudaFuncAttributeMaxDynamicSharedMemorySize, 65536);

    k_zero<<<1, 1>>>();
    k_embed<<<NOBS / 32, 256>>>(logits, noise_full, W, bias);
    dim3 grid(NOBS / 128, NOBS / 128);
    k_pairwise<<<grid, 256, 65536>>>();
    k_loss<<<NBATCH / 32, 256>>>(pij, noise_i, noise_j, logits, W, iv, jv, out);
}

// round 4
// speedup vs baseline: 1.6495x; 1.6495x over previous
#include <cuda_runtime.h>
#include <cuda_bf16.h>
#include <math.h>
#include <cstdint>

#define NOBS   8192
#define NTOP   128
#define NDIM   64
#define NBATCH 8192

// ------------------------- scratch (no cudaMalloc) -------------------------
__device__ __nv_bfloat16 g_Xhi[NOBS * NDIM];
__device__ __nv_bfloat16 g_Xlo[NOBS * NDIM];
__device__ float  g_sq[NOBS];
__device__ double g_part;

#define SMEM_SWZ128(o) ((o) ^ (((o) >> 3) & 0x70))

// ------------------------- gumbel softmax ----------------------------------
__device__ __forceinline__ float gumbel_of(float u) {
    return -logf(-logf(u + 1e-9f) + 1e-9f);
}
__device__ __forceinline__ void gumbel_softmax4(const float* __restrict__ lrow,
                                                const float* __restrict__ nrow,
                                                int lane, float z[4]) {
    float m = -1e30f;
#pragma unroll
    for (int c = 0; c < 4; c++) {
        int t = lane + 32 * c;
        z[c] = lrow[t] + gumbel_of(nrow[t]);
        m = fmaxf(m, z[c]);
    }
#pragma unroll
    for (int o = 16; o > 0; o >>= 1) m = fmaxf(m, __shfl_xor_sync(0xffffffffu, m, o));
    float s = 0.f;
#pragma unroll
    for (int c = 0; c < 4; c++) { z[c] = expf(z[c] - m); s += z[c]; }
#pragma unroll
    for (int o = 16; o > 0; o >>= 1) s += __shfl_xor_sync(0xffffffffu, s, o);
    float inv = 1.f / s;
#pragma unroll
    for (int c = 0; c < 4; c++) z[c] *= inv;
}

// ---------------------------------------------------------------------------
// K1: embed. One row per warp. Writes bf16 hi/lo split of x + fp32 sq norm.
// ---------------------------------------------------------------------------
__global__ void __launch_bounds__(256) k_embed(const float* __restrict__ logits,
                                               const float* __restrict__ noise,
                                               const float* __restrict__ W,
                                               const float* __restrict__ bias) {
    __shared__ float Wsm[NDIM * 129];
    __shared__ float zsm[8 * NTOP];
    int tid = threadIdx.x, w = tid >> 5, lane = tid & 31;
    if (blockIdx.x == 0 && tid == 0) g_part = 0.0;

    for (int idx = tid; idx < NDIM * NTOP; idx += 256)
        Wsm[(idx >> 7) * 129 + (idx & 127)] = W[idx];
    __syncthreads();

    int row = blockIdx.x * 8 + w;
    float z[4];
    gumbel_softmax4(logits + (size_t)row * NTOP, noise + (size_t)row * NTOP, lane, z);
#pragma unroll
    for (int c = 0; c < 4; c++) zsm[w * NTOP + lane + 32 * c] = z[c];
    __syncwarp();

    float acc = 0.f;
#pragma unroll
    for (int h = 0; h < 2; h++) {
        int d = lane + 32 * h;
        float xd = bias[d];
        const float* zp = &zsm[w * NTOP];
        const float* wp = &Wsm[d * 129];
#pragma unroll 8
        for (int t = 0; t < NTOP; t++) xd = fmaf(zp[t], wp[t], xd);
        __nv_bfloat16 hi = __float2bfloat16(xd);
        g_Xhi[(size_t)row * NDIM + d] = hi;
        g_Xlo[(size_t)row * NDIM + d] = __float2bfloat16(xd - __bfloat162float(hi));
        acc = fmaf(xd, xd, acc);
    }
#pragma unroll
    for (int o = 16; o > 0; o >>= 1) acc += __shfl_xor_sync(0xffffffffu, acc, o);
    if (lane == 0) g_sq[row] = acc;
}

// ---------------------------------------------------------------------------
// K2: pairwise partition sum via mma.sync bf16 HMMA (hi/lo split, 3 products).
// 128x128 tile per CTA, bi <= bj only, off-diag counted x2. Register accums.
// smem tiles: [128 rows][128B] SW128-swizzled -> conflict-free fragment LDS.
// ---------------------------------------------------------------------------
#define T_AHI 0
#define T_ALO 16384
#define T_BHI 32768
#define T_BLO 49152
#define T_SQA 65536
#define T_SQB 66048
#define T_RED 66560
#define SMEM_PW 66624

__device__ __forceinline__ void mma16816(float c[4], const uint32_t a[4], const uint32_t b[2]) {
    asm volatile(
        "mma.sync.aligned.m16n8k16.row.col.f32.bf16.bf16.f32 "
        "{%0,%1,%2,%3}, {%4,%5,%6,%7}, {%8,%9}, {%0,%1,%2,%3};"
        : "+f"(c[0]), "+f"(c[1]), "+f"(c[2]), "+f"(c[3])
        : "r"(a[0]), "r"(a[1]), "r"(a[2]), "r"(a[3]), "r"(b[0]), "r"(b[1]));
}

__global__ void __launch_bounds__(256) k_pairwise_hmma() {
    int bj = blockIdx.x, bi = blockIdx.y;
    if (bi > bj) return;
    bool diag = (bi == bj);

    extern __shared__ char sm[];
    int tid = threadIdx.x;

    {   // fill 4 tiles (each 128 rows x 128B) with SW128 swizzle; coalesced uint4
        const char* src[4] = {
            (const char*)(g_Xhi + (size_t)bi * 128 * NDIM),
            (const char*)(g_Xlo + (size_t)bi * 128 * NDIM),
            (const char*)(g_Xhi + (size_t)bj * 128 * NDIM),
            (const char*)(g_Xlo + (size_t)bj * 128 * NDIM)};
        const int dst[4] = {T_AHI, T_ALO, T_BHI, T_BLO};
#pragma unroll
        for (int tl = 0; tl < 4; tl++)
#pragma unroll
            for (int it = 0; it < 4; it++) {
                int off = (it * 256 + tid) * 16;
                *(uint4*)(sm + dst[tl] + SMEM_SWZ128((uint32_t)off)) =
                    *(const uint4*)(src[tl] + off);
            }
        if (tid < 128) ((float*)(sm + T_SQA))[tid] = g_sq[bi * 128 + tid];
        else           ((float*)(sm + T_SQB))[tid - 128] = g_sq[bj * 128 + tid - 128];
    }
    __syncthreads();

    int lane = tid & 31, w = tid >> 5;
    int mw = (w >> 2) * 64;   // warp m offset (0 or 64)
    int nw = (w & 3) * 32;    // warp n offset (0,32,64,96)
    int g = lane >> 2, t = lane & 3;

    float c[4][4][4];
#pragma unroll
    for (int mt = 0; mt < 4; mt++)
#pragma unroll
        for (int nt = 0; nt < 4; nt++)
#pragma unroll
            for (int q = 0; q < 4; q++) c[mt][nt][q] = 0.f;

    // virtual K = 192: ks 0-3 hi.hi, 4-7 hi.lo, 8-11 lo.hi (16 k per step)
#pragma unroll
    for (int ks = 0; ks < 12; ks++) {
        int aoff = (ks < 8) ? T_AHI : T_ALO;
        int boff = (ks >= 4 && ks < 8) ? T_BLO : T_BHI;
        // swizzled byte cols for this thread (row&7 == g for all fragment rows)
        int c0 = ((ks & 3) * 32 + 4 * t) ^ (g << 4);
        int c1 = ((ks & 3) * 32 + 4 * t + 16) ^ (g << 4);

        uint32_t a[4][4];
#pragma unroll
        for (int mt = 0; mt < 4; mt++) {
            const char* r0 = sm + aoff + (mw + mt * 16 + g) * 128;
            const char* r1 = r0 + 8 * 128;
            a[mt][0] = *(const uint32_t*)(r0 + c0);
            a[mt][1] = *(const uint32_t*)(r1 + c0);
            a[mt][2] = *(const uint32_t*)(r0 + c1);
            a[mt][3] = *(const uint32_t*)(r1 + c1);
        }
        uint32_t b[4][2];
#pragma unroll
        for (int nt = 0; nt < 4; nt++) {
            const char* rn = sm + boff + (nw + nt * 8 + g) * 128;
            b[nt][0] = *(const uint32_t*)(rn + c0);
            b[nt][1] = *(const uint32_t*)(rn + c1);
        }
#pragma unroll
        for (int mt = 0; mt < 4; mt++)
#pragma unroll
            for (int nt = 0; nt < 4; nt++) mma16816(c[mt][nt], a[mt], b[nt]);
    }

    // epilogue: d = sa + sb - 2*dot ; v = 1/(1+d) ; mask diagonal
    const float* sqA = (const float*)(sm + T_SQA);
    const float* sqB = (const float*)(sm + T_SQB);
    float acc = 0.f;
#pragma unroll
    for (int mt = 0; mt < 4; mt++) {
        int m0 = mw + mt * 16 + g;
        float sa0 = sqA[m0], sa1 = sqA[m0 + 8];
#pragma unroll
        for (int nt = 0; nt < 4; nt++) {
            int n0 = nw + nt * 8 + 2 * t;
            float sb0 = sqB[n0], sb1 = sqB[n0 + 1];
            float d00 = sa0 + sb0 - 2.f * c[mt][nt][0];
            float d01 = sa0 + sb1 - 2.f * c[mt][nt][1];
            float d10 = sa1 + sb0 - 2.f * c[mt][nt][2];
            float d11 = sa1 + sb1 - 2.f * c[mt][nt][3];
            float v00 = __fdividef(1.f, 1.f + d00);
            float v01 = __fdividef(1.f, 1.f + d01);
            float v10 = __fdividef(1.f, 1.f + d10);
            float v11 = __fdividef(1.f, 1.f + d11);
            if (diag) {
                if (m0 == n0) v00 = 0.f;
                if (m0 == n0 + 1) v01 = 0.f;
                if (m0 + 8 == n0) v10 = 0.f;
                if (m0 + 8 == n0 + 1) v11 = 0.f;
            }
            acc += (v00 + v01) + (v10 + v11);
        }
    }

#pragma unroll
    for (int o = 16; o > 0; o >>= 1) acc += __shfl_xor_sync(0xffffffffu, acc, o);
    float* red = (float*)(sm + T_RED);
    if (lane == 0) red[w] = acc;
    __syncthreads();
    if (tid == 0) {
        float s = 0.f;
#pragma unroll
        for (int q = 0; q < 8; q++) s += red[q];
        atomicAdd(&g_part, (double)s * (diag ? 1.0 : 2.0));
    }
}

// ---------------------------------------------------------------------------
// K3: per-batch loss. One element per warp.
// ---------------------------------------------------------------------------
__global__ void __launch_bounds__(256) k_loss(const float* __restrict__ pij,
                                              const float* __restrict__ noise_i,
                                              const float* __restrict__ noise_j,
                                              const float* __restrict__ logits,
                                              const float* __restrict__ W,
                                              const int* __restrict__ iv,
                                              const int* __restrict__ jv,
                                              float* __restrict__ out) {
    __shared__ float Wsm[NDIM * 129];
    __shared__ float zsm[8 * NTOP];
    int tid = threadIdx.x, w = tid >> 5, lane = tid & 31;

    for (int idx = tid; idx < NDIM * NTOP; idx += 256)
        Wsm[(idx >> 7) * 129 + (idx & 127)] = W[idx];
    __syncthreads();

    int el = blockIdx.x * 8 + w;
    int ri = iv[el], rj = jv[el];
    float zi[4], zj[4];
    gumbel_softmax4(logits + (size_t)ri * NTOP, noise_i + (size_t)el * NTOP, lane, zi);
    gumbel_softmax4(logits + (size_t)rj * NTOP, noise_j + (size_t)el * NTOP, lane, zj);
#pragma unroll
    for (int c = 0; c < 4; c++) zsm[w * NTOP + lane + 32 * c] = zi[c] - zj[c];
    __syncwarp();

    float acc = 0.f;
#pragma unroll
    for (int h = 0; h < 2; h++) {
        int d = lane + 32 * h;
        float xd = 0.f;
        const float* zp = &zsm[w * NTOP];
        const float* wp = &Wsm[d * 129];
#pragma unroll 8
        for (int t = 0; t < NTOP; t++) xd = fmaf(zp[t], wp[t], xd);
        acc = fmaf(xd, xd, acc);
    }
#pragma unroll
    for (int o = 16; o > 0; o >>= 1) acc += __shfl_xor_sync(0xffffffffu, acc, o);

    if (lane == 0) {
        float den = (float)NDIM + acc;
        float p = pij[el];
        out[el] = p * (logf(p) + logf(den) + logf((float)g_part));
    }
}

extern "C" void kernel_launch(void* const* d_in, const int* in_sizes, int n_in,
                              void* d_out, int out_size) {
    const float* pij        = (const float*)d_in[0];
    const float* noise_full = (const float*)d_in[1];
    const float* noise_i    = (const float*)d_in[2];
    const float* noise_j    = (const float*)d_in[3];
    const float* logits     = (const float*)d_in[4];
    const float* W          = (const float*)d_in[5];
    const float* bias       = (const float*)d_in[6];
    const int*   iv         = (const int*)d_in[7];
    const int*   jv         = (const int*)d_in[8];
    float* out = (float*)d_out;

    cudaFuncSetAttribute(k_pairwise_hmma, cudaFuncAttributeMaxDynamicSharedMemorySize, SMEM_PW);

    k_embed<<<NOBS / 8, 256>>>(logits, noise_full, W, bias);
    dim3 grid(NOBS / 128, NOBS / 128);
    k_pairwise_hmma<<<grid, 256, SMEM_PW>>>();
    k_loss<<<NBATCH / 8, 256>>>(pij, noise_i, noise_j, logits, W, iv, jv, out);
}

// round 5
// speedup vs baseline: 1.8515x; 1.1225x over previous
#include <cuda_runtime.h>
#include <cuda_bf16.h>
#include <math.h>
#include <cstdint>

#define NOBS   8192
#define NTOP   128
#define NDIM   64
#define NBATCH 8192

// ------------------------- scratch (no cudaMalloc) -------------------------
__device__ __nv_bfloat16 g_Xhi[NOBS * NDIM];
__device__ __nv_bfloat16 g_Xlo[NOBS * NDIM];
__device__ float  g_sq[NOBS];
__device__ double g_part;

#define SMEM_SWZ128(o) ((o) ^ (((o) >> 3) & 0x70))
#define WPAD 132   // W row stride in floats: mult of 4 (float4), 132%32=4 -> conflict-free

// ------------------------- gumbel softmax ----------------------------------
__device__ __forceinline__ float gumbel_of(float u) {
    return -logf(-logf(u + 1e-9f) + 1e-9f);
}
__device__ __forceinline__ void gumbel_softmax4(const float* __restrict__ lrow,
                                                const float* __restrict__ nrow,
                                                int lane, float z[4]) {
    float m = -1e30f;
#pragma unroll
    for (int c = 0; c < 4; c++) {
        int t = lane + 32 * c;
        z[c] = lrow[t] + gumbel_of(nrow[t]);
        m = fmaxf(m, z[c]);
    }
#pragma unroll
    for (int o = 16; o > 0; o >>= 1) m = fmaxf(m, __shfl_xor_sync(0xffffffffu, m, o));
    float s = 0.f;
#pragma unroll
    for (int c = 0; c < 4; c++) { z[c] = expf(z[c] - m); s += z[c]; }
#pragma unroll
    for (int o = 16; o > 0; o >>= 1) s += __shfl_xor_sync(0xffffffffu, s, o);
    float inv = 1.f / s;
#pragma unroll
    for (int c = 0; c < 4; c++) z[c] *= inv;
}

// 128-length dot: zsm (broadcast) . W row (float4, 4 accumulators)
__device__ __forceinline__ float dot128(const float4* __restrict__ zp4,
                                        const float4* __restrict__ wp4) {
    float a0 = 0.f, a1 = 0.f, a2 = 0.f, a3 = 0.f;
#pragma unroll
    for (int q = 0; q < 32; q++) {
        float4 zv = zp4[q], wv = wp4[q];
        a0 = fmaf(zv.x, wv.x, a0);
        a1 = fmaf(zv.y, wv.y, a1);
        a2 = fmaf(zv.z, wv.z, a2);
        a3 = fmaf(zv.w, wv.w, a3);
    }
    return (a0 + a1) + (a2 + a3);
}

// ---------------------------------------------------------------------------
// K1: embed. One row per warp. Writes bf16 hi/lo split of x + fp32 sq norm.
// ---------------------------------------------------------------------------
__global__ void __launch_bounds__(256) k_embed(const float* __restrict__ logits,
                                               const float* __restrict__ noise,
                                               const float* __restrict__ W,
                                               const float* __restrict__ bias) {
    __shared__ float Wsm[NDIM * WPAD];
    __shared__ float zsm[8 * NTOP];
    int tid = threadIdx.x, w = tid >> 5, lane = tid & 31;
    if (blockIdx.x == 0 && tid == 0) g_part = 0.0;

    for (int idx = tid; idx < NDIM * NTOP; idx += 256)
        Wsm[(idx >> 7) * WPAD + (idx & 127)] = W[idx];
    __syncthreads();

    int row = blockIdx.x * 8 + w;
    float z[4];
    gumbel_softmax4(logits + (size_t)row * NTOP, noise + (size_t)row * NTOP, lane, z);
#pragma unroll
    for (int c = 0; c < 4; c++) zsm[w * NTOP + lane + 32 * c] = z[c];
    __syncwarp();

    const float4* zp4 = (const float4*)&zsm[w * NTOP];
    float acc = 0.f;
#pragma unroll
    for (int h = 0; h < 2; h++) {
        int d = lane + 32 * h;
        float xd = bias[d] + dot128(zp4, (const float4*)&Wsm[d * WPAD]);
        __nv_bfloat16 hi = __float2bfloat16(xd);
        g_Xhi[(size_t)row * NDIM + d] = hi;
        g_Xlo[(size_t)row * NDIM + d] = __float2bfloat16(xd - __bfloat162float(hi));
        acc = fmaf(xd, xd, acc);
    }
#pragma unroll
    for (int o = 16; o > 0; o >>= 1) acc += __shfl_xor_sync(0xffffffffu, acc, o);
    if (lane == 0) g_sq[row] = acc;
}

// ---------------------------------------------------------------------------
// K2: pairwise partition sum via mma.sync bf16 HMMA (hi/lo split, 3 products).
// Triangular grid of 2080 CTAs (bi <= bj), off-diag counted x2.
// Per k-chunk: load aHi,bHi,bLo -> hi.hi + hi.lo; overwrite a with aLo -> lo.hi.
// ---------------------------------------------------------------------------
#define T_AHI 0
#define T_ALO 16384
#define T_BHI 32768
#define T_BLO 49152
#define T_SQA 65536
#define T_SQB 66048
#define T_RED 66560
#define SMEM_PW 66624

__device__ __forceinline__ void mma16816(float c[4], const uint32_t a[4], const uint32_t b[2]) {
    asm volatile(
        "mma.sync.aligned.m16n8k16.row.col.f32.bf16.bf16.f32 "
        "{%0,%1,%2,%3}, {%4,%5,%6,%7}, {%8,%9}, {%0,%1,%2,%3};"
        : "+f"(c[0]), "+f"(c[1]), "+f"(c[2]), "+f"(c[3])
        : "r"(a[0]), "r"(a[1]), "r"(a[2]), "r"(a[3]), "r"(b[0]), "r"(b[1]));
}

__global__ void __launch_bounds__(256, 2) k_pairwise_hmma() {
    // triangular decode: f(r) = r*(129-r)/2 tiles before row r
    int k = blockIdx.x;
    int bi;
    {
        float s = sqrtf((float)(129 * 129 - 8 * k));
        bi = (int)((129.0f - s) * 0.5f);
        while ((bi + 1) * (129 - (bi + 1)) / 2 <= k) bi++;
        while (bi * (129 - bi) / 2 > k) bi--;
    }
    int bj = bi + (k - bi * (129 - bi) / 2);
    bool diag = (bi == bj);

    extern __shared__ char sm[];
    int tid = threadIdx.x;

    {   // fill 4 tiles (each 128 rows x 128B) with SW128 swizzle; coalesced uint4
        const char* src[4] = {
            (const char*)(g_Xhi + (size_t)bi * 128 * NDIM),
            (const char*)(g_Xlo + (size_t)bi * 128 * NDIM),
            (const char*)(g_Xhi + (size_t)bj * 128 * NDIM),
            (const char*)(g_Xlo + (size_t)bj * 128 * NDIM)};
        const int dst[4] = {T_AHI, T_ALO, T_BHI, T_BLO};
#pragma unroll
        for (int tl = 0; tl < 4; tl++)
#pragma unroll
            for (int it = 0; it < 4; it++) {
                int off = (it * 256 + tid) * 16;
                *(uint4*)(sm + dst[tl] + SMEM_SWZ128((uint32_t)off)) =
                    *(const uint4*)(src[tl] + off);
            }
        if (tid < 128) ((float*)(sm + T_SQA))[tid] = g_sq[bi * 128 + tid];
        else           ((float*)(sm + T_SQB))[tid - 128] = g_sq[bj * 128 + tid - 128];
    }
    __syncthreads();

    int lane = tid & 31, w = tid >> 5;
    int mw = (w >> 2) * 64;   // warp m offset (0 or 64)
    int nw = (w & 3) * 32;    // warp n offset (0,32,64,96)
    int g = lane >> 2, t = lane & 3;

    float c[4][4][4];
#pragma unroll
    for (int mt = 0; mt < 4; mt++)
#pragma unroll
        for (int nt = 0; nt < 4; nt++)
#pragma unroll
            for (int q = 0; q < 4; q++) c[mt][nt][q] = 0.f;

#pragma unroll
    for (int kc = 0; kc < 4; kc++) {
        int c0 = (kc * 32 + 4 * t) ^ (g << 4);
        int c1 = (kc * 32 + 4 * t + 16) ^ (g << 4);

        uint32_t b_hi[4][2], b_lo[4][2];
#pragma unroll
        for (int nt = 0; nt < 4; nt++) {
            const char* rh = sm + T_BHI + (nw + nt * 8 + g) * 128;
            const char* rl = sm + T_BLO + (nw + nt * 8 + g) * 128;
            b_hi[nt][0] = *(const uint32_t*)(rh + c0);
            b_hi[nt][1] = *(const uint32_t*)(rh + c1);
            b_lo[nt][0] = *(const uint32_t*)(rl + c0);
            b_lo[nt][1] = *(const uint32_t*)(rl + c1);
        }
        uint32_t a[4][4];
#pragma unroll
        for (int mt = 0; mt < 4; mt++) {
            const char* r0 = sm + T_AHI + (mw + mt * 16 + g) * 128;
            const char* r1 = r0 + 8 * 128;
            a[mt][0] = *(const uint32_t*)(r0 + c0);
            a[mt][1] = *(const uint32_t*)(r1 + c0);
            a[mt][2] = *(const uint32_t*)(r0 + c1);
            a[mt][3] = *(const uint32_t*)(r1 + c1);
        }
#pragma unroll
        for (int mt = 0; mt < 4; mt++)
#pragma unroll
            for (int nt = 0; nt < 4; nt++) {
                mma16816(c[mt][nt], a[mt], b_hi[nt]);   // hi.hi
                mma16816(c[mt][nt], a[mt], b_lo[nt]);   // hi.lo
            }
#pragma unroll
        for (int mt = 0; mt < 4; mt++) {                // overwrite with A-lo
            const char* r0 = sm + T_ALO + (mw + mt * 16 + g) * 128;
            const char* r1 = r0 + 8 * 128;
            a[mt][0] = *(const uint32_t*)(r0 + c0);
            a[mt][1] = *(const uint32_t*)(r1 + c0);
            a[mt][2] = *(const uint32_t*)(r0 + c1);
            a[mt][3] = *(const uint32_t*)(r1 + c1);
        }
#pragma unroll
        for (int mt = 0; mt < 4; mt++)
#pragma unroll
            for (int nt = 0; nt < 4; nt++)
                mma16816(c[mt][nt], a[mt], b_hi[nt]);   // lo.hi
    }

    // epilogue: d = sa + sb - 2*dot ; v = 1/(1+d) ; mask diagonal
    const float* sqA = (const float*)(sm + T_SQA);
    const float* sqB = (const float*)(sm + T_SQB);
    float acc = 0.f;
#pragma unroll
    for (int mt = 0; mt < 4; mt++) {
        int m0 = mw + mt * 16 + g;
        float sa0 = sqA[m0], sa1 = sqA[m0 + 8];
#pragma unroll
        for (int nt = 0; nt < 4; nt++) {
            int n0 = nw + nt * 8 + 2 * t;
            float sb0 = sqB[n0], sb1 = sqB[n0 + 1];
            float d00 = sa0 + sb0 - 2.f * c[mt][nt][0];
            float d01 = sa0 + sb1 - 2.f * c[mt][nt][1];
            float d10 = sa1 + sb0 - 2.f * c[mt][nt][2];
            float d11 = sa1 + sb1 - 2.f * c[mt][nt][3];
            float v00 = __fdividef(1.f, 1.f + d00);
            float v01 = __fdividef(1.f, 1.f + d01);
            float v10 = __fdividef(1.f, 1.f + d10);
            float v11 = __fdividef(1.f, 1.f + d11);
            if (diag) {
                if (m0 == n0) v00 = 0.f;
                if (m0 == n0 + 1) v01 = 0.f;
                if (m0 + 8 == n0) v10 = 0.f;
                if (m0 + 8 == n0 + 1) v11 = 0.f;
            }
            acc += (v00 + v01) + (v10 + v11);
        }
    }

#pragma unroll
    for (int o = 16; o > 0; o >>= 1) acc += __shfl_xor_sync(0xffffffffu, acc, o);
    float* red = (float*)(sm + T_RED);
    if (lane == 0) red[w] = acc;
    __syncthreads();
    if (tid == 0) {
        float s = 0.f;
#pragma unroll
        for (int q = 0; q < 8; q++) s += red[q];
        atomicAdd(&g_part, (double)s * (diag ? 1.0 : 2.0));
    }
}

// ---------------------------------------------------------------------------
// K3: per-batch loss. One element per warp, float4 + multi-acc dot.
// ---------------------------------------------------------------------------
__global__ void __launch_bounds__(256) k_loss(const float* __restrict__ pij,
                                              const float* __restrict__ noise_i,
                                              const float* __restrict__ noise_j,
                                              const float* __restrict__ logits,
                                              const float* __restrict__ W,
                                              const int* __restrict__ iv,
                                              const int* __restrict__ jv,
                                              float* __restrict__ out) {
    __shared__ float Wsm[NDIM * WPAD];
    __shared__ float zsm[8 * NTOP];
    int tid = threadIdx.x, w = tid >> 5, lane = tid & 31;

    for (int idx = tid; idx < NDIM * NTOP; idx += 256)
        Wsm[(idx >> 7) * WPAD + (idx & 127)] = W[idx];
    __syncthreads();

    int el = blockIdx.x * 8 + w;
    int ri = iv[el], rj = jv[el];
    float zi[4], zj[4];
    gumbel_softmax4(logits + (size_t)ri * NTOP, noise_i + (size_t)el * NTOP, lane, zi);
    gumbel_softmax4(logits + (size_t)rj * NTOP, noise_j + (size_t)el * NTOP, lane, zj);
#pragma unroll
    for (int c = 0; c < 4; c++) zsm[w * NTOP + lane + 32 * c] = zi[c] - zj[c];
    __syncwarp();

    const float4* zp4 = (const float4*)&zsm[w * NTOP];
    float acc = 0.f;
#pragma unroll
    for (int h = 0; h < 2; h++) {
        int d = lane + 32 * h;
        float xd = dot128(zp4, (const float4*)&Wsm[d * WPAD]);
        acc = fmaf(xd, xd, acc);
    }
#pragma unroll
    for (int o = 16; o > 0; o >>= 1) acc += __shfl_xor_sync(0xffffffffu, acc, o);

    if (lane == 0) {
        float den = (float)NDIM + acc;
        float p = pij[el];
        out[el] = p * (logf(p) + logf(den) + logf((float)g_part));
    }
}

extern "C" void kernel_launch(void* const* d_in, const int* in_sizes, int n_in,
                              void* d_out, int out_size) {
    const float* pij        = (const float*)d_in[0];
    const float* noise_full = (const float*)d_in[1];
    const float* noise_i    = (const float*)d_in[2];
    const float* noise_j    = (const float*)d_in[3];
    const float* logits     = (const float*)d_in[4];
    const float* W          = (const float*)d_in[5];
    const float* bias       = (const float*)d_in[6];
    const int*   iv         = (const int*)d_in[7];
    const int*   jv         = (const int*)d_in[8];
    float* out = (float*)d_out;

    cudaFuncSetAttribute(k_pairwise_hmma, cudaFuncAttributeMaxDynamicSharedMemorySize, SMEM_PW);

    k_embed<<<NOBS / 8, 256>>>(logits, noise_full, W, bias);
    k_pairwise_hmma<<<2080, 256, SMEM_PW>>>();
    k_loss<<<NBATCH / 8, 256>>>(pij, noise_i, noise_j, logits, W, iv, jv, out);
}

// round 6
// speedup vs baseline: 2.2015x; 1.1890x over previous
#include <cuda_runtime.h>
#include <cuda_bf16.h>
#include <math.h>
#include <cstdint>

#define NOBS   8192
#define NTOP   128
#define NDIM   64
#define NBATCH 8192

// ------------------------- scratch (no cudaMalloc) -------------------------
__device__ float  g_X[NOBS * NDIM];   // tf32-rounded embedded points
__device__ float  g_sq[NOBS];         // squared norms of the ROUNDED points
__device__ double g_part;

#define WPAD 132

// ---------------- fast log for t in (1e-9, 1]: MUFU + log1p fix ------------
__device__ __forceinline__ float fast_log_unit(float t) {
    float s = t - 1.0f;                      // |s| small near 1
    // log1p(s) = s*(1 - s/2 + s^2/3 - s^3/4 + s^4/5 - s^5/6), |s|<=0.094
    float p = fmaf(s, -0.16666667f, 0.2f);
    p = fmaf(s, p, -0.25f);
    p = fmaf(s, p, 0.33333333f);
    p = fmaf(s, p, -0.5f);
    p = fmaf(s, p, 1.0f);
    p = s * p;
    float lg = __logf(t);                    // MUFU path, fine away from 1
    return (t > 0.90625f) ? p : lg;
}

// gumbel softmax, ratio form: softmax(l+g)_k = (e^{l_k}/w_k) / sum
// with w_k = -log(u_k + eps) + eps  (identical math to the reference)
__device__ __forceinline__ void gumbel_softmax4(const float* __restrict__ lrow,
                                                const float* __restrict__ nrow,
                                                int lane, float z[4]) {
    float s = 0.f;
#pragma unroll
    for (int c = 0; c < 4; c++) {
        int t = lane + 32 * c;
        float w = -fast_log_unit(nrow[t] + 1e-9f) + 1e-9f;
        z[c] = __fdividef(__expf(lrow[t]), w);
        s += z[c];
    }
#pragma unroll
    for (int o = 16; o > 0; o >>= 1) s += __shfl_xor_sync(0xffffffffu, s, o);
    float inv = __fdividef(1.f, s);
#pragma unroll
    for (int c = 0; c < 4; c++) z[c] *= inv;
}

// 128-length dot with bounded unroll (keeps regs low)
__device__ __forceinline__ float dot128(const float4* __restrict__ zp4,
                                        const float4* __restrict__ wp4) {
    float a0 = 0.f, a1 = 0.f, a2 = 0.f, a3 = 0.f;
#pragma unroll 8
    for (int q = 0; q < 32; q++) {
        float4 zv = zp4[q], wv = wp4[q];
        a0 = fmaf(zv.x, wv.x, a0);
        a1 = fmaf(zv.y, wv.y, a1);
        a2 = fmaf(zv.z, wv.z, a2);
        a3 = fmaf(zv.w, wv.w, a3);
    }
    return (a0 + a1) + (a2 + a3);
}

__device__ __forceinline__ float tf32_round(float x) {
    uint32_t r;
    asm("cvt.rna.tf32.f32 %0, %1;" : "=r"(r) : "f"(x));
    return __uint_as_float(r);
}

// ---------------------------------------------------------------------------
// K1: embed. One row per warp. Stores tf32-rounded x + sq norm of rounded x.
// ---------------------------------------------------------------------------
__global__ void __launch_bounds__(256, 4) k_embed(const float* __restrict__ logits,
                                                  const float* __restrict__ noise,
                                                  const float* __restrict__ W,
                                                  const float* __restrict__ bias) {
    __shared__ float Wsm[NDIM * WPAD];
    __shared__ float zsm[8 * NTOP];
    int tid = threadIdx.x, w = tid >> 5, lane = tid & 31;
    if (blockIdx.x == 0 && tid == 0) g_part = 0.0;

    for (int idx = tid; idx < NDIM * NTOP; idx += 256)
        Wsm[(idx >> 7) * WPAD + (idx & 127)] = W[idx];
    __syncthreads();

    int row = blockIdx.x * 8 + w;
    float z[4];
    gumbel_softmax4(logits + (size_t)row * NTOP, noise + (size_t)row * NTOP, lane, z);
#pragma unroll
    for (int c = 0; c < 4; c++) zsm[w * NTOP + lane + 32 * c] = z[c];
    __syncwarp();

    const float4* zp4 = (const float4*)&zsm[w * NTOP];
    float acc = 0.f;
#pragma unroll
    for (int h = 0; h < 2; h++) {
        int d = lane + 32 * h;
        float xd = bias[d] + dot128(zp4, (const float4*)&Wsm[d * WPAD]);
        float xr = tf32_round(xd);
        g_X[(size_t)row * NDIM + d] = xr;
        acc = fmaf(xr, xr, acc);
    }
#pragma unroll
    for (int o = 16; o > 0; o >>= 1) acc += __shfl_xor_sync(0xffffffffu, acc, o);
    if (lane == 0) g_sq[row] = acc;
}

// ---------------------------------------------------------------------------
// K2: pairwise partition sum via mma.sync tf32 (single product, exact on
// tf32-rounded inputs). Triangular grid (2080 CTAs), off-diag counted x2.
// ---------------------------------------------------------------------------
#define T_A   0
#define T_B   32768
#define T_SQA 65536
#define T_SQB 66048
#define T_RED 66560
#define SMEM_PW 66624

__device__ __forceinline__ void mma_tf32(float c[4], const uint32_t a[4], const uint32_t b[2]) {
    asm volatile(
        "mma.sync.aligned.m16n8k8.row.col.f32.tf32.tf32.f32 "
        "{%0,%1,%2,%3}, {%4,%5,%6,%7}, {%8,%9}, {%0,%1,%2,%3};"
        : "+f"(c[0]), "+f"(c[1]), "+f"(c[2]), "+f"(c[3])
        : "r"(a[0]), "r"(a[1]), "r"(a[2]), "r"(a[3]), "r"(b[0]), "r"(b[1]));
}

__global__ void __launch_bounds__(256, 2) k_pairwise_tf32() {
    // triangular decode
    int k = blockIdx.x;
    int bi;
    {
        float s = sqrtf((float)(129 * 129 - 8 * k));
        bi = (int)((129.0f - s) * 0.5f);
        while ((bi + 1) * (129 - (bi + 1)) / 2 <= k) bi++;
        while (bi * (129 - bi) / 2 > k) bi--;
    }
    int bj = bi + (k - bi * (129 - bi) / 2);
    bool diag = (bi == bj);

    extern __shared__ char sm[];
    int tid = threadIdx.x;

    {   // fill A,B tiles: [128 rows][256B] with 16B-granular row swizzle
        const uint4* srcA = (const uint4*)(g_X + (size_t)bi * 128 * NDIM);
        const uint4* srcB = (const uint4*)(g_X + (size_t)bj * 128 * NDIM);
#pragma unroll
        for (int it = 0; it < 8; it++) {
            int idx = it * 256 + tid;
            int off = idx * 16;
            int row = off >> 8;
            uint32_t sw = (uint32_t)(off & ~255) | (uint32_t)((off & 255) ^ ((row & 7) << 4));
            *(uint4*)(sm + T_A + sw) = srcA[idx];
            *(uint4*)(sm + T_B + sw) = srcB[idx];
        }
        if (tid < 128) ((float*)(sm + T_SQA))[tid] = g_sq[bi * 128 + tid];
        else           ((float*)(sm + T_SQB))[tid - 128] = g_sq[bj * 128 + tid - 128];
    }
    __syncthreads();

    int lane = tid & 31, w = tid >> 5;
    int mw = (w >> 2) * 64;   // warp m offset (0 or 64)
    int nw = (w & 3) * 32;    // warp n offset (0,32,64,96)
    int g = lane >> 2, t = lane & 3;

    float c[4][4][4];
#pragma unroll
    for (int mt = 0; mt < 4; mt++)
#pragma unroll
        for (int nt = 0; nt < 4; nt++)
#pragma unroll
            for (int q = 0; q < 4; q++) c[mt][nt][q] = 0.f;

#pragma unroll
    for (int ks = 0; ks < 8; ks++) {       // K = 64, 8 per mma
        int c0 = (32 * ks + 4 * t) ^ (g << 4);
        int c1 = (32 * ks + 4 * t + 16) ^ (g << 4);

        uint32_t b[4][2];
#pragma unroll
        for (int nt = 0; nt < 4; nt++) {
            const char* rn = sm + T_B + (nw + nt * 8 + g) * 256;
            b[nt][0] = *(const uint32_t*)(rn + c0);
            b[nt][1] = *(const uint32_t*)(rn + c1);
        }
        uint32_t a[4][4];
#pragma unroll
        for (int mt = 0; mt < 4; mt++) {
            const char* r0 = sm + T_A + (mw + mt * 16 + g) * 256;
            const char* r1 = r0 + 8 * 256;
            a[mt][0] = *(const uint32_t*)(r0 + c0);
            a[mt][1] = *(const uint32_t*)(r1 + c0);
            a[mt][2] = *(const uint32_t*)(r0 + c1);
            a[mt][3] = *(const uint32_t*)(r1 + c1);
        }
#pragma unroll
        for (int mt = 0; mt < 4; mt++)
#pragma unroll
            for (int nt = 0; nt < 4; nt++)
                mma_tf32(c[mt][nt], a[mt], b[nt]);
    }

    // epilogue: d = sa + sb - 2*dot ; v = 1/(1+d) ; mask diagonal
    const float* sqA = (const float*)(sm + T_SQA);
    const float* sqB = (const float*)(sm + T_SQB);
    float acc = 0.f;
#pragma unroll
    for (int mt = 0; mt < 4; mt++) {
        int m0 = mw + mt * 16 + g;
        float sa0 = sqA[m0], sa1 = sqA[m0 + 8];
#pragma unroll
        for (int nt = 0; nt < 4; nt++) {
            int n0 = nw + nt * 8 + 2 * t;
            float sb0 = sqB[n0], sb1 = sqB[n0 + 1];
            float d00 = sa0 + sb0 - 2.f * c[mt][nt][0];
            float d01 = sa0 + sb1 - 2.f * c[mt][nt][1];
            float d10 = sa1 + sb0 - 2.f * c[mt][nt][2];
            float d11 = sa1 + sb1 - 2.f * c[mt][nt][3];
            float v00 = __fdividef(1.f, 1.f + d00);
            float v01 = __fdividef(1.f, 1.f + d01);
            float v10 = __fdividef(1.f, 1.f + d10);
            float v11 = __fdividef(1.f, 1.f + d11);
            if (diag) {
                if (m0 == n0) v00 = 0.f;
                if (m0 == n0 + 1) v01 = 0.f;
                if (m0 + 8 == n0) v10 = 0.f;
                if (m0 + 8 == n0 + 1) v11 = 0.f;
            }
            acc += (v00 + v01) + (v10 + v11);
        }
    }

#pragma unroll
    for (int o = 16; o > 0; o >>= 1) acc += __shfl_xor_sync(0xffffffffu, acc, o);
    float* red = (float*)(sm + T_RED);
    if (lane == 0) red[w] = acc;
    __syncthreads();
    if (tid == 0) {
        float s = 0.f;
#pragma unroll
        for (int q = 0; q < 8; q++) s += red[q];
        atomicAdd(&g_part, (double)s * (diag ? 1.0 : 2.0));
    }
}

// ---------------------------------------------------------------------------
// K3: per-batch loss. One element per warp.
// ---------------------------------------------------------------------------
__global__ void __launch_bounds__(256, 4) k_loss(const float* __restrict__ pij,
                                                 const float* __restrict__ noise_i,
                                                 const float* __restrict__ noise_j,
                                                 const float* __restrict__ logits,
                                                 const float* __restrict__ W,
                                                 const int* __restrict__ iv,
                                                 const int* __restrict__ jv,
                                                 float* __restrict__ out) {
    __shared__ float Wsm[NDIM * WPAD];
    __shared__ float zsm[8 * NTOP];
    int tid = threadIdx.x, w = tid >> 5, lane = tid & 31;

    for (int idx = tid; idx < NDIM * NTOP; idx += 256)
        Wsm[(idx >> 7) * WPAD + (idx & 127)] = W[idx];
    __syncthreads();

    int el = blockIdx.x * 8 + w;
    int ri = iv[el], rj = jv[el];
    float zi[4], zj[4];
    gumbel_softmax4(logits + (size_t)ri * NTOP, noise_i + (size_t)el * NTOP, lane, zi);
    gumbel_softmax4(logits + (size_t)rj * NTOP, noise_j + (size_t)el * NTOP, lane, zj);
#pragma unroll
    for (int c = 0; c < 4; c++) zsm[w * NTOP + lane + 32 * c] = zi[c] - zj[c];
    __syncwarp();

    const float4* zp4 = (const float4*)&zsm[w * NTOP];
    float acc = 0.f;
#pragma unroll
    for (int h = 0; h < 2; h++) {
        int d = lane + 32 * h;
        float xd = dot128(zp4, (const float4*)&Wsm[d * WPAD]);
        acc = fmaf(xd, xd, acc);
    }
#pragma unroll
    for (int o = 16; o > 0; o >>= 1) acc += __shfl_xor_sync(0xffffffffu, acc, o);

    if (lane == 0) {
        float den = (float)NDIM + acc;
        float p = pij[el];
        out[el] = p * (logf(p) + logf(den) + logf((float)g_part));
    }
}

extern "C" void kernel_launch(void* const* d_in, const int* in_sizes, int n_in,
                              void* d_out, int out_size) {
    const float* pij        = (const float*)d_in[0];
    const float* noise_full = (const float*)d_in[1];
    const float* noise_i    = (const float*)d_in[2];
    const float* noise_j    = (const float*)d_in[3];
    const float* logits     = (const float*)d_in[4];
    const float* W          = (const float*)d_in[5];
    const float* bias       = (const float*)d_in[6];
    const int*   iv         = (const int*)d_in[7];
    const int*   jv         = (const int*)d_in[8];
    float* out = (float*)d_out;

    cudaFuncSetAttribute(k_pairwise_tf32, cudaFuncAttributeMaxDynamicSharedMemorySize, SMEM_PW);

    k_embed<<<NOBS / 8, 256>>>(logits, noise_full, W, bias);
    k_pairwise_tf32<<<2080, 256, SMEM_PW>>>();
    k_loss<<<NBATCH / 8, 256>>>(pij, noise_i, noise_j, logits, W, iv, jv, out);
}

// round 7
// speedup vs baseline: 2.6665x; 1.2112x over previous
#include <cuda_runtime.h>
#include <cuda_bf16.h>
#include <math.h>
#include <cstdint>

#define NOBS   8192
#define NTOP   128
#define NDIM   64
#define NBATCH 8192
#define NROWS  (NOBS + NBATCH)   // 16384 rows through the shared GEMM

// ------------------------- scratch (no cudaMalloc) -------------------------
__device__ float  g_Z[NROWS * NTOP];   // softmax rows (full) + diff rows (batch)
__device__ float  g_X[NOBS * NDIM];    // tf32-rounded embedded points
__device__ float  g_Xd[NBATCH * NDIM]; // fp32 xi-xj rows
__device__ float  g_sq[NOBS];
__device__ double g_part;

// ---------------- fast log for t in (1e-9, 1]: MUFU + log1p fix ------------
__device__ __forceinline__ float fast_log_unit(float t) {
    float s = t - 1.0f;
    float p = fmaf(s, -0.16666667f, 0.2f);
    p = fmaf(s, p, -0.25f);
    p = fmaf(s, p, 0.33333333f);
    p = fmaf(s, p, -0.5f);
    p = fmaf(s, p, 1.0f);
    p = s * p;
    float lg = __logf(t);
    return (t > 0.90625f) ? p : lg;
}

// gumbel softmax, ratio form: softmax(l+g)_k = (e^{l_k}/w_k) / sum,
// w_k = -log(u_k + eps) + eps  (identical math to reference)
__device__ __forceinline__ void gumbel_softmax4(const float* __restrict__ lrow,
                                                const float* __restrict__ nrow,
                                                int lane, float z[4]) {
    float s = 0.f;
#pragma unroll
    for (int c = 0; c < 4; c++) {
        int t = lane + 32 * c;
        float w = -fast_log_unit(nrow[t] + 1e-9f) + 1e-9f;
        z[c] = __fdividef(__expf(lrow[t]), w);
        s += z[c];
    }
#pragma unroll
    for (int o = 16; o > 0; o >>= 1) s += __shfl_xor_sync(0xffffffffu, s, o);
    float inv = __fdividef(1.f, s);
#pragma unroll
    for (int c = 0; c < 4; c++) z[c] *= inv;
}

__device__ __forceinline__ float tf32_round(float x) {
    uint32_t r;
    asm("cvt.rna.tf32.f32 %0, %1;" : "=r"(r) : "f"(x));
    return __uint_as_float(r);
}
__device__ __forceinline__ uint32_t tf32_hi(float x) {
    uint32_t r;
    asm("cvt.rna.tf32.f32 %0, %1;" : "=r"(r) : "f"(x));
    return r;
}

// ---------------------------------------------------------------------------
// K0: z rows. Warp -> one row. Rows [0,8192): full softmax rows.
// Rows [8192,16384): zdiff = softmax(logits[i]) - softmax(logits[j]).
// Pure stream: no block smem, no syncthreads, max occupancy.
// ---------------------------------------------------------------------------
__global__ void __launch_bounds__(256) k_z(const float* __restrict__ logits,
                                           const float* __restrict__ noise_full,
                                           const float* __restrict__ noise_i,
                                           const float* __restrict__ noise_j,
                                           const int* __restrict__ iv,
                                           const int* __restrict__ jv) {
    int tid = threadIdx.x, w = tid >> 5, lane = tid & 31;
    int row = blockIdx.x * 8 + w;
    if (blockIdx.x == 0 && tid == 0) g_part = 0.0;

    if (row < NOBS) {
        float z[4];
        gumbel_softmax4(logits + (size_t)row * NTOP, noise_full + (size_t)row * NTOP, lane, z);
#pragma unroll
        for (int c = 0; c < 4; c++) g_Z[(size_t)row * NTOP + lane + 32 * c] = z[c];
    } else {
        int el = row - NOBS;
        int ri = iv[el], rj = jv[el];
        float zi[4], zj[4];
        gumbel_softmax4(logits + (size_t)ri * NTOP, noise_i + (size_t)el * NTOP, lane, zi);
        gumbel_softmax4(logits + (size_t)rj * NTOP, noise_j + (size_t)el * NTOP, lane, zj);
#pragma unroll
        for (int c = 0; c < 4; c++)
            g_Z[(size_t)row * NTOP + lane + 32 * c] = zi[c] - zj[c];
    }
}

// ---------------------------------------------------------------------------
// K1: X = Z @ W^T via tf32 mma, hi/lo split on BOTH operands (3 products ->
// fp32-equivalent). 64 rows per block, 256 blocks. Rows < 8192: tf32-round
// and store to g_X. Rows >= 8192: store raw fp32 diff to g_Xd.
// smem: Zs [64 rows][512B] + Ws [64 rows][512B], swizzled.
// ---------------------------------------------------------------------------
#define G_ZS 0
#define G_WS 32768
#define SMEM_G 65536

__device__ __forceinline__ void mma_tf32(float c[4], const uint32_t a[4], const uint32_t b[2]) {
    asm volatile(
        "mma.sync.aligned.m16n8k8.row.col.f32.tf32.tf32.f32 "
        "{%0,%1,%2,%3}, {%4,%5,%6,%7}, {%8,%9}, {%0,%1,%2,%3};"
        : "+f"(c[0]), "+f"(c[1]), "+f"(c[2]), "+f"(c[3])
        : "r"(a[0]), "r"(a[1]), "r"(a[2]), "r"(a[3]), "r"(b[0]), "r"(b[1]));
}

__global__ void __launch_bounds__(256, 2) k_gemm(const float* __restrict__ W) {
    extern __shared__ char sm[];
    int tid = threadIdx.x;
    int base = blockIdx.x * 64;

    {   // fill: rows are 512B; swizzle XOR ((row&7)<<4) on the low 9 bits
        const uint4* srcZ = (const uint4*)(g_Z + (size_t)base * NTOP);
        const uint4* srcW = (const uint4*)W;
#pragma unroll
        for (int it = 0; it < 8; it++) {
            int idx = it * 256 + tid;
            int off = idx * 16;
            int row = off >> 9;
            uint32_t sw = (uint32_t)(off & ~511) | (uint32_t)((off & 511) ^ ((row & 7) << 4));
            *(uint4*)(sm + G_ZS + sw) = srcZ[idx];
            *(uint4*)(sm + G_WS + sw) = srcW[idx];
        }
    }
    __syncthreads();

    int lane = tid & 31, w = tid >> 5;
    int mw = (w >> 2) * 32;   // warp m offset (0 or 32)
    int nw = (w & 3) * 16;    // warp n offset (0,16,32,48)
    int g = lane >> 2, t = lane & 3;

    float c[2][2][4];
#pragma unroll
    for (int mt = 0; mt < 2; mt++)
#pragma unroll
        for (int nt = 0; nt < 2; nt++)
#pragma unroll
            for (int q = 0; q < 4; q++) c[mt][nt][q] = 0.f;

#pragma unroll
    for (int ks = 0; ks < 16; ks++) {
        int c0 = (ks * 32 + 4 * t) ^ (g << 4);
        int c1 = (ks * 32 + 4 * t + 16) ^ (g << 4);

        uint32_t bh[2][2], bl[2][2];
#pragma unroll
        for (int nt = 0; nt < 2; nt++) {
            const char* rn = sm + G_WS + (nw + nt * 8 + g) * 512;
            float b0 = *(const float*)(rn + c0);
            float b1 = *(const float*)(rn + c1);
            bh[nt][0] = tf32_hi(b0);
            bh[nt][1] = tf32_hi(b1);
            bl[nt][0] = tf32_hi(b0 - __uint_as_float(bh[nt][0]));
            bl[nt][1] = tf32_hi(b1 - __uint_as_float(bh[nt][1]));
        }
        uint32_t ah[2][4], al[2][4];
#pragma unroll
        for (int mt = 0; mt < 2; mt++) {
            const char* r0 = sm + G_ZS + (mw + mt * 16 + g) * 512;
            const char* r1 = r0 + 8 * 512;
            float a0 = *(const float*)(r0 + c0);
            float a1 = *(const float*)(r1 + c0);
            float a2 = *(const float*)(r0 + c1);
            float a3 = *(const float*)(r1 + c1);
            ah[mt][0] = tf32_hi(a0); al[mt][0] = tf32_hi(a0 - __uint_as_float(ah[mt][0]));
            ah[mt][1] = tf32_hi(a1); al[mt][1] = tf32_hi(a1 - __uint_as_float(ah[mt][1]));
            ah[mt][2] = tf32_hi(a2); al[mt][2] = tf32_hi(a2 - __uint_as_float(ah[mt][2]));
            ah[mt][3] = tf32_hi(a3); al[mt][3] = tf32_hi(a3 - __uint_as_float(ah[mt][3]));
        }
#pragma unroll
        for (int mt = 0; mt < 2; mt++)
#pragma unroll
            for (int nt = 0; nt < 2; nt++) {
                mma_tf32(c[mt][nt], ah[mt], bh[nt]);   // hi.hi
                mma_tf32(c[mt][nt], al[mt], bh[nt]);   // lo.hi
                mma_tf32(c[mt][nt], ah[mt], bl[nt]);   // hi.lo
            }
    }

    bool zrows = (base < NOBS);
#pragma unroll
    for (int mt = 0; mt < 2; mt++) {
        int m0 = base + mw + mt * 16 + g;
#pragma unroll
        for (int nt = 0; nt < 2; nt++) {
            int n0 = nw + nt * 8 + 2 * t;
            if (zrows) {
                g_X[(size_t)m0 * NDIM + n0]           = tf32_round(c[mt][nt][0]);
                g_X[(size_t)m0 * NDIM + n0 + 1]       = tf32_round(c[mt][nt][1]);
                g_X[(size_t)(m0 + 8) * NDIM + n0]     = tf32_round(c[mt][nt][2]);
                g_X[(size_t)(m0 + 8) * NDIM + n0 + 1] = tf32_round(c[mt][nt][3]);
            } else {
                int mm = m0 - NOBS;
                g_Xd[(size_t)mm * NDIM + n0]           = c[mt][nt][0];
                g_Xd[(size_t)mm * NDIM + n0 + 1]       = c[mt][nt][1];
                g_Xd[(size_t)(mm + 8) * NDIM + n0]     = c[mt][nt][2];
                g_Xd[(size_t)(mm + 8) * NDIM + n0 + 1] = c[mt][nt][3];
            }
        }
    }
}

// ---------------------------------------------------------------------------
// K2: squared norms of the rounded points. Warp per row.
// ---------------------------------------------------------------------------
__global__ void __launch_bounds__(256) k_sq() {
    int tid = threadIdx.x, w = tid >> 5, lane = tid & 31;
    int row = blockIdx.x * 8 + w;
    float x0 = g_X[(size_t)row * NDIM + lane];
    float x1 = g_X[(size_t)row * NDIM + lane + 32];
    float acc = fmaf(x0, x0, x1 * x1);
#pragma unroll
    for (int o = 16; o > 0; o >>= 1) acc += __shfl_xor_sync(0xffffffffu, acc, o);
    if (lane == 0) g_sq[row] = acc;
}

// ---------------------------------------------------------------------------
// K3: pairwise partition sum via tf32 mma (exact on tf32-rounded inputs).
// Triangular grid (2080 CTAs), off-diag counted x2.  [unchanged from R5]
// ---------------------------------------------------------------------------
#define T_A   0
#define T_B   32768
#define T_SQA 65536
#define T_SQB 66048
#define T_RED 66560
#define SMEM_PW 66624

__global__ void __launch_bounds__(256, 2) k_pairwise_tf32() {
    int k = blockIdx.x;
    int bi;
    {
        float s = sqrtf((float)(129 * 129 - 8 * k));
        bi = (int)((129.0f - s) * 0.5f);
        while ((bi + 1) * (129 - (bi + 1)) / 2 <= k) bi++;
        while (bi * (129 - bi) / 2 > k) bi--;
    }
    int bj = bi + (k - bi * (129 - bi) / 2);
    bool diag = (bi == bj);

    extern __shared__ char sm[];
    int tid = threadIdx.x;

    {
        const uint4* srcA = (const uint4*)(g_X + (size_t)bi * 128 * NDIM);
        const uint4* srcB = (const uint4*)(g_X + (size_t)bj * 128 * NDIM);
#pragma unroll
        for (int it = 0; it < 8; it++) {
            int idx = it * 256 + tid;
            int off = idx * 16;
            int row = off >> 8;
            uint32_t sw = (uint32_t)(off & ~255) | (uint32_t)((off & 255) ^ ((row & 7) << 4));
            *(uint4*)(sm + T_A + sw) = srcA[idx];
            *(uint4*)(sm + T_B + sw) = srcB[idx];
        }
        if (tid < 128) ((float*)(sm + T_SQA))[tid] = g_sq[bi * 128 + tid];
        else           ((float*)(sm + T_SQB))[tid - 128] = g_sq[bj * 128 + tid - 128];
    }
    __syncthreads();

    int lane = tid & 31, w = tid >> 5;
    int mw = (w >> 2) * 64;
    int nw = (w & 3) * 32;
    int g = lane >> 2, t = lane & 3;

    float c[4][4][4];
#pragma unroll
    for (int mt = 0; mt < 4; mt++)
#pragma unroll
        for (int nt = 0; nt < 4; nt++)
#pragma unroll
            for (int q = 0; q < 4; q++) c[mt][nt][q] = 0.f;

#pragma unroll
    for (int ks = 0; ks < 8; ks++) {
        int c0 = (32 * ks + 4 * t) ^ (g << 4);
        int c1 = (32 * ks + 4 * t + 16) ^ (g << 4);

        uint32_t b[4][2];
#pragma unroll
        for (int nt = 0; nt < 4; nt++) {
            const char* rn = sm + T_B + (nw + nt * 8 + g) * 256;
            b[nt][0] = *(const uint32_t*)(rn + c0);
            b[nt][1] = *(const uint32_t*)(rn + c1);
        }
        uint32_t a[4][4];
#pragma unroll
        for (int mt = 0; mt < 4; mt++) {
            const char* r0 = sm + T_A + (mw + mt * 16 + g) * 256;
            const char* r1 = r0 + 8 * 256;
            a[mt][0] = *(const uint32_t*)(r0 + c0);
            a[mt][1] = *(const uint32_t*)(r1 + c0);
            a[mt][2] = *(const uint32_t*)(r0 + c1);
            a[mt][3] = *(const uint32_t*)(r1 + c1);
        }
#pragma unroll
        for (int mt = 0; mt < 4; mt++)
#pragma unroll
            for (int nt = 0; nt < 4; nt++)
                mma_tf32(c[mt][nt], a[mt], b[nt]);
    }

    const float* sqA = (const float*)(sm + T_SQA);
    const float* sqB = (const float*)(sm + T_SQB);
    float acc = 0.f;
#pragma unroll
    for (int mt = 0; mt < 4; mt++) {
        int m0 = mw + mt * 16 + g;
        float sa0 = sqA[m0], sa1 = sqA[m0 + 8];
#pragma unroll
        for (int nt = 0; nt < 4; nt++) {
            int n0 = nw + nt * 8 + 2 * t;
            float sb0 = sqB[n0], sb1 = sqB[n0 + 1];
            float d00 = sa0 + sb0 - 2.f * c[mt][nt][0];
            float d01 = sa0 + sb1 - 2.f * c[mt][nt][1];
            float d10 = sa1 + sb0 - 2.f * c[mt][nt][2];
            float d11 = sa1 + sb1 - 2.f * c[mt][nt][3];
            float v00 = __fdividef(1.f, 1.f + d00);
            float v01 = __fdividef(1.f, 1.f + d01);
            float v10 = __fdividef(1.f, 1.f + d10);
            float v11 = __fdividef(1.f, 1.f + d11);
            if (diag) {
                if (m0 == n0) v00 = 0.f;
                if (m0 == n0 + 1) v01 = 0.f;
                if (m0 + 8 == n0) v10 = 0.f;
                if (m0 + 8 == n0 + 1) v11 = 0.f;
            }
            acc += (v00 + v01) + (v10 + v11);
        }
    }

#pragma unroll
    for (int o = 16; o > 0; o >>= 1) acc += __shfl_xor_sync(0xffffffffu, acc, o);
    float* red = (float*)(sm + T_RED);
    if (lane == 0) red[w] = acc;
    __syncthreads();
    if (tid == 0) {
        float s = 0.f;
#pragma unroll
        for (int q = 0; q < 8; q++) s += red[q];
        atomicAdd(&g_part, (double)s * (diag ? 1.0 : 2.0));
    }
}

// ---------------------------------------------------------------------------
// K4: loss finish. Warp per element: den = 64 + ||xdiff||^2.
// ---------------------------------------------------------------------------
__global__ void __launch_bounds__(256) k_loss_fin(const float* __restrict__ pij,
                                                  float* __restrict__ out) {
    int tid = threadIdx.x, w = tid >> 5, lane = tid & 31;
    int el = blockIdx.x * 8 + w;
    float d0 = g_Xd[(size_t)el * NDIM + lane];
    float d1 = g_Xd[(size_t)el * NDIM + lane + 32];
    float acc = fmaf(d0, d0, d1 * d1);
#pragma unroll
    for (int o = 16; o > 0; o >>= 1) acc += __shfl_xor_sync(0xffffffffu, acc, o);
    if (lane == 0) {
        float den = (float)NDIM + acc;
        float p = pij[el];
        out[el] = p * (logf(p) + logf(den) + logf((float)g_part));
    }
}

extern "C" void kernel_launch(void* const* d_in, const int* in_sizes, int n_in,
                              void* d_out, int out_size) {
    const float* pij        = (const float*)d_in[0];
    const float* noise_full = (const float*)d_in[1];
    const float* noise_i    = (const float*)d_in[2];
    const float* noise_j    = (const float*)d_in[3];
    const float* logits     = (const float*)d_in[4];
    const float* W          = (const float*)d_in[5];
    const int*   iv         = (const int*)d_in[7];
    const int*   jv         = (const int*)d_in[8];
    float* out = (float*)d_out;

    cudaFuncSetAttribute(k_gemm, cudaFuncAttributeMaxDynamicSharedMemorySize, SMEM_G);
    cudaFuncSetAttribute(k_pairwise_tf32, cudaFuncAttributeMaxDynamicSharedMemorySize, SMEM_PW);

    k_z<<<NROWS / 8, 256>>>(logits, noise_full, noise_i, noise_j, iv, jv);
    k_gemm<<<NROWS / 64, 256, SMEM_G>>>(W);
    k_sq<<<NOBS / 8, 256>>>();
    k_pairwise_tf32<<<2080, 256, SMEM_PW>>>();
    k_loss_fin<<<NBATCH / 8, 256>>>(pij, out);
}

// round 10
// speedup vs baseline: 2.7539x; 1.0328x over previous
#include <cuda_runtime.h>
#include <cuda_bf16.h>
#include <math.h>
#include <cstdint>

#define NOBS   8192
#define NTOP   128
#define NDIM   64
#define NBATCH 8192
#define NROWS  (NOBS + NBATCH)
#define NTILE  64           // number of 128x128 tiles per dim (8192/128)
#define NTRI   2080         // triangular tile count = 64*65/2
#define NPCTA  296          // persistent CTAs (2 per SM)

// ------------------------- scratch (no cudaMalloc) -------------------------
__device__ float  g_Z[NROWS * NTOP];
__device__ float  g_X[NOBS * NDIM];    // tf32-rounded embedded points
__device__ float  g_sq[NOBS];          // sq norms of rounded points (atomic-accumulated)
__device__ float  g_den[NBATCH];       // ||xi-xj||^2 per batch element
__device__ double g_part;

// ------------------------- helpers -----------------------------------------
__device__ __forceinline__ uint32_t smem_u32(const void* p) {
    uint32_t a;
    asm("{ .reg .u64 t; cvta.to.shared.u64 t, %1; cvt.u32.u64 %0, t; }" : "=r"(a) : "l"(p));
    return a;
}
__device__ __forceinline__ void cp16(uint32_t dst, const void* src) {
    asm volatile("{ .reg .u64 g; cvta.to.global.u64 g, %1; "
                 "cp.async.cg.shared.global [%0], [g], 16; }"
                 :: "r"(dst), "l"(src));
}
#define CP_COMMIT() asm volatile("cp.async.commit_group;" ::: "memory")
#define CP_WAIT0()  asm volatile("cp.async.wait_group 0;" ::: "memory")

__device__ __forceinline__ float fast_log_unit(float t) {
    float s = t - 1.0f;
    float p = fmaf(s, -0.16666667f, 0.2f);
    p = fmaf(s, p, -0.25f);
    p = fmaf(s, p, 0.33333333f);
    p = fmaf(s, p, -0.5f);
    p = fmaf(s, p, 1.0f);
    p = s * p;
    float lg = __logf(t);
    return (t > 0.90625f) ? p : lg;
}

__device__ __forceinline__ void gumbel_softmax4(const float* __restrict__ lrow,
                                                const float* __restrict__ nrow,
                                                int lane, float z[4]) {
    float s = 0.f;
#pragma unroll
    for (int c = 0; c < 4; c++) {
        int t = lane + 32 * c;
        float w = -fast_log_unit(nrow[t] + 1e-9f) + 1e-9f;
        z[c] = __fdividef(__expf(lrow[t]), w);
        s += z[c];
    }
#pragma unroll
    for (int o = 16; o > 0; o >>= 1) s += __shfl_xor_sync(0xffffffffu, s, o);
    float inv = __fdividef(1.f, s);
#pragma unroll
    for (int c = 0; c < 4; c++) z[c] *= inv;
}

__device__ __forceinline__ float tf32_round(float x) {
    uint32_t r;
    asm("cvt.rna.tf32.f32 %0, %1;" : "=r"(r) : "f"(x));
    return __uint_as_float(r);
}
__device__ __forceinline__ uint32_t tf32_hi(float x) {
    uint32_t r;
    asm("cvt.rna.tf32.f32 %0, %1;" : "=r"(r) : "f"(x));
    return r;
}
__device__ __forceinline__ void mma_tf32(float c[4], const uint32_t a[4], const uint32_t b[2]) {
    asm volatile(
        "mma.sync.aligned.m16n8k8.row.col.f32.tf32.tf32.f32 "
        "{%0,%1,%2,%3}, {%4,%5,%6,%7}, {%8,%9}, {%0,%1,%2,%3};"
        : "+f"(c[0]), "+f"(c[1]), "+f"(c[2]), "+f"(c[3])
        : "r"(a[0]), "r"(a[1]), "r"(a[2]), "r"(a[3]), "r"(b[0]), "r"(b[1]));
}
__device__ __forceinline__ float rcp_approx(float x) {
    float r;
    asm("rcp.approx.f32 %0, %1;" : "=f"(r) : "f"(x));
    return r;
}

// ---------------------------------------------------------------------------
// K0: softmax rows (full) + diff rows (batch); zero g_sq / g_den / g_part.
// ---------------------------------------------------------------------------
__global__ void __launch_bounds__(256) k_z(const float* __restrict__ logits,
                                           const float* __restrict__ noise_full,
                                           const float* __restrict__ noise_i,
                                           const float* __restrict__ noise_j,
                                           const int* __restrict__ iv,
                                           const int* __restrict__ jv) {
    int tid = threadIdx.x, w = tid >> 5, lane = tid & 31;
    int row = blockIdx.x * 8 + w;
    int gz = blockIdx.x * 256 + tid;
    if (gz < NOBS)   g_sq[gz] = 0.f;
    if (gz < NBATCH) g_den[gz] = 0.f;
    if (gz == 0)     g_part = 0.0;

    if (row < NOBS) {
        float z[4];
        gumbel_softmax4(logits + (size_t)row * NTOP, noise_full + (size_t)row * NTOP, lane, z);
#pragma unroll
        for (int c = 0; c < 4; c++) g_Z[(size_t)row * NTOP + lane + 32 * c] = z[c];
    } else {
        int el = row - NOBS;
        int ri = iv[el], rj = jv[el];
        float zi[4], zj[4];
        gumbel_softmax4(logits + (size_t)ri * NTOP, noise_i + (size_t)el * NTOP, lane, zi);
        gumbel_softmax4(logits + (size_t)rj * NTOP, noise_j + (size_t)el * NTOP, lane, zj);
#pragma unroll
        for (int c = 0; c < 4; c++)
            g_Z[(size_t)row * NTOP + lane + 32 * c] = zi[c] - zj[c];
    }
}

// ---------------------------------------------------------------------------
// K1: X = Z @ W^T (tf32 x3, fp32-equivalent). Fused epilogue:
//   rows < NOBS: store rounded x to g_X, atomic row-sumsq -> g_sq
//   rows >= NOBS: atomic row-sumsq (raw fp32) -> g_den
// ---------------------------------------------------------------------------
#define G_ZS 0
#define G_WS 32768
#define SMEM_G 65536

__global__ void __launch_bounds__(256, 2) k_gemm(const float* __restrict__ W) {
    extern __shared__ char sm[];
    int tid = threadIdx.x;
    int base = blockIdx.x * 64;

    {
        const uint4* srcZ = (const uint4*)(g_Z + (size_t)base * NTOP);
        const uint4* srcW = (const uint4*)W;
#pragma unroll
        for (int it = 0; it < 8; it++) {
            int idx = it * 256 + tid;
            int off = idx * 16;
            int row = off >> 9;
            uint32_t sw = (uint32_t)(off & ~511) | (uint32_t)((off & 511) ^ ((row & 7) << 4));
            *(uint4*)(sm + G_ZS + sw) = srcZ[idx];
            *(uint4*)(sm + G_WS + sw) = srcW[idx];
        }
    }
    __syncthreads();

    int lane = tid & 31, w = tid >> 5;
    int mw = (w >> 2) * 32;
    int nw = (w & 3) * 16;
    int g = lane >> 2, t = lane & 3;

    float c[2][2][4];
#pragma unroll
    for (int mt = 0; mt < 2; mt++)
#pragma unroll
        for (int nt = 0; nt < 2; nt++)
#pragma unroll
            for (int q = 0; q < 4; q++) c[mt][nt][q] = 0.f;

#pragma unroll
    for (int ks = 0; ks < 16; ks++) {
        int c0 = (ks * 32 + 4 * t) ^ (g << 4);
        int c1 = (ks * 32 + 4 * t + 16) ^ (g << 4);

        uint32_t bh[2][2], bl[2][2];
#pragma unroll
        for (int nt = 0; nt < 2; nt++) {
            const char* rn = sm + G_WS + (nw + nt * 8 + g) * 512;
            float b0 = *(const float*)(rn + c0);
            float b1 = *(const float*)(rn + c1);
            bh[nt][0] = tf32_hi(b0);
            bh[nt][1] = tf32_hi(b1);
            bl[nt][0] = tf32_hi(b0 - __uint_as_float(bh[nt][0]));
            bl[nt][1] = tf32_hi(b1 - __uint_as_float(bh[nt][1]));
        }
        uint32_t ah[2][4], al[2][4];
#pragma unroll
        for (int mt = 0; mt < 2; mt++) {
            const char* r0 = sm + G_ZS + (mw + mt * 16 + g) * 512;
            const char* r1 = r0 + 8 * 512;
            float a0 = *(const float*)(r0 + c0);
            float a1 = *(const float*)(r1 + c0);
            float a2 = *(const float*)(r0 + c1);
            float a3 = *(const float*)(r1 + c1);
            ah[mt][0] = tf32_hi(a0); al[mt][0] = tf32_hi(a0 - __uint_as_float(ah[mt][0]));
            ah[mt][1] = tf32_hi(a1); al[mt][1] = tf32_hi(a1 - __uint_as_float(ah[mt][1]));
            ah[mt][2] = tf32_hi(a2); al[mt][2] = tf32_hi(a2 - __uint_as_float(ah[mt][2]));
            ah[mt][3] = tf32_hi(a3); al[mt][3] = tf32_hi(a3 - __uint_as_float(ah[mt][3]));
        }
#pragma unroll
        for (int mt = 0; mt < 2; mt++)
#pragma unroll
            for (int nt = 0; nt < 2; nt++) {
                mma_tf32(c[mt][nt], ah[mt], bh[nt]);
                mma_tf32(c[mt][nt], al[mt], bh[nt]);
                mma_tf32(c[mt][nt], ah[mt], bl[nt]);
            }
    }

    bool zrows = (base < NOBS);
#pragma unroll
    for (int mt = 0; mt < 2; mt++) {
        int m0 = base + mw + mt * 16 + g;
        float r0 = 0.f, r1 = 0.f;
#pragma unroll
        for (int nt = 0; nt < 2; nt++) {
            int n0 = nw + nt * 8 + 2 * t;
            float v00 = c[mt][nt][0], v01 = c[mt][nt][1];
            float v10 = c[mt][nt][2], v11 = c[mt][nt][3];
            if (zrows) {
                v00 = tf32_round(v00); v01 = tf32_round(v01);
                v10 = tf32_round(v10); v11 = tf32_round(v11);
                g_X[(size_t)m0 * NDIM + n0]           = v00;
                g_X[(size_t)m0 * NDIM + n0 + 1]       = v01;
                g_X[(size_t)(m0 + 8) * NDIM + n0]     = v10;
                g_X[(size_t)(m0 + 8) * NDIM + n0 + 1] = v11;
            }
            r0 += fmaf(v00, v00, v01 * v01);
            r1 += fmaf(v10, v10, v11 * v11);
        }
        r0 += __shfl_xor_sync(0xffffffffu, r0, 1);
        r0 += __shfl_xor_sync(0xffffffffu, r0, 2);
        r1 += __shfl_xor_sync(0xffffffffu, r1, 1);
        r1 += __shfl_xor_sync(0xffffffffu, r1, 2);
        if (t == 0) {
            if (zrows) {
                atomicAdd(&g_sq[m0], r0);
                atomicAdd(&g_sq[m0 + 8], r1);
            } else {
                atomicAdd(&g_den[m0 - NOBS], r0);
                atomicAdd(&g_den[m0 + 8 - NOBS], r1);
            }
        }
    }
}

// ---------------------------------------------------------------------------
// K2: persistent pairwise partition sum. 296 CTAs, consecutive triangular
// tile ranges (row-major, 64 tile-rows). A panel resident; B double-buffered
// via cp.async. Diagonal tiles reuse A as B.
// ---------------------------------------------------------------------------
#define P_A    0
#define P_B0   32768
#define P_B1   65536
#define P_RED  98304
#define SMEM_PW 98368

__device__ __forceinline__ void fill_async(uint32_t smbase, const float* gsrc, int tid) {
    const char* src = (const char*)gsrc;
#pragma unroll
    for (int it = 0; it < 8; it++) {
        int off = (it * 256 + tid) * 16;
        int row = off >> 8;
        uint32_t sw = (uint32_t)(off & ~255) | (uint32_t)((off & 255) ^ ((row & 7) << 4));
        cp16(smbase + sw, src + off);
    }
}

__device__ __forceinline__ void tile_compute(char* sm, uint32_t boff,
                                             int bi, int bj, bool diag, int tid) {
    int lane = tid & 31, w = tid >> 5;
    int mw = (w >> 2) * 64;
    int nw = (w & 3) * 32;
    int g = lane >> 2, t = lane & 3;

    float c[4][4][4];
#pragma unroll
    for (int mt = 0; mt < 4; mt++)
#pragma unroll
        for (int nt = 0; nt < 4; nt++)
#pragma unroll
            for (int q = 0; q < 4; q++) c[mt][nt][q] = 0.f;

#pragma unroll
    for (int ks = 0; ks < 8; ks++) {
        int c0 = (32 * ks + 4 * t) ^ (g << 4);
        int c1 = (32 * ks + 4 * t + 16) ^ (g << 4);

        uint32_t b[4][2];
#pragma unroll
        for (int nt = 0; nt < 4; nt++) {
            const char* rn = sm + boff + (nw + nt * 8 + g) * 256;
            b[nt][0] = *(const uint32_t*)(rn + c0);
            b[nt][1] = *(const uint32_t*)(rn + c1);
        }
        uint32_t a[4][4];
#pragma unroll
        for (int mt = 0; mt < 4; mt++) {
            const char* r0 = sm + P_A + (mw + mt * 16 + g) * 256;
            const char* r1 = r0 + 8 * 256;
            a[mt][0] = *(const uint32_t*)(r0 + c0);
            a[mt][1] = *(const uint32_t*)(r1 + c0);
            a[mt][2] = *(const uint32_t*)(r0 + c1);
            a[mt][3] = *(const uint32_t*)(r1 + c1);
        }
#pragma unroll
        for (int mt = 0; mt < 4; mt++)
#pragma unroll
            for (int nt = 0; nt < 4; nt++)
                mma_tf32(c[mt][nt], a[mt], b[nt]);
    }

    float sb0[4], sb1[4];
#pragma unroll
    for (int nt = 0; nt < 4; nt++) {
        int n0 = nw + nt * 8 + 2 * t;
        sb0[nt] = g_sq[bj * 128 + n0];
        sb1[nt] = g_sq[bj * 128 + n0 + 1];
    }
    float acc = 0.f;
#pragma unroll
    for (int mt = 0; mt < 4; mt++) {
        int m0 = mw + mt * 16 + g;
        float sa0 = g_sq[bi * 128 + m0];
        float sa1 = g_sq[bi * 128 + m0 + 8];
#pragma unroll
        for (int nt = 0; nt < 4; nt++) {
            int n0 = nw + nt * 8 + 2 * t;
            float v00 = rcp_approx(fmaf(-2.f, c[mt][nt][0], 1.f + sa0 + sb0[nt]));
            float v01 = rcp_approx(fmaf(-2.f, c[mt][nt][1], 1.f + sa0 + sb1[nt]));
            float v10 = rcp_approx(fmaf(-2.f, c[mt][nt][2], 1.f + sa1 + sb0[nt]));
            float v11 = rcp_approx(fmaf(-2.f, c[mt][nt][3], 1.f + sa1 + sb1[nt]));
            if (diag) {
                if (m0 == n0) v00 = 0.f;
                if (m0 == n0 + 1) v01 = 0.f;
                if (m0 + 8 == n0) v10 = 0.f;
                if (m0 + 8 == n0 + 1) v11 = 0.f;
            }
            acc += (v00 + v01) + (v10 + v11);
        }
    }
#pragma unroll
    for (int o = 16; o > 0; o >>= 1) acc += __shfl_xor_sync(0xffffffffu, acc, o);
    float* red = (float*)(sm + P_RED);
    if (lane == 0) red[w] = acc;
    __syncthreads();
    if (tid == 0) {
        float s = 0.f;
#pragma unroll
        for (int q = 0; q < 8; q++) s += red[q];
        atomicAdd(&g_part, (double)s * (diag ? 1.0 : 2.0));
    }
}

__global__ void __launch_bounds__(256, 2) k_pairwise() {
    extern __shared__ char sm[];
    uint32_t smb = smem_u32(sm);
    int tid = threadIdx.x;
    int cid = blockIdx.x;

    int t0 = (NTRI * cid) / NPCTA;
    int t1 = (NTRI * (cid + 1)) / NPCTA;

    // decode t0 -> (bi, bj): row bi has (64 - bi) tiles
    int bi = 0, rem = t0;
    while (rem >= NTILE - bi) { rem -= NTILE - bi; bi++; }
    int bj = bi + rem;

    fill_async(smb + P_A, g_X + (size_t)bi * 128 * NDIM, tid);
    int curbuf = 0, nextbuf = 0;
    if (bj != bi) {
        fill_async(smb + P_B0, g_X + (size_t)bj * 128 * NDIM, tid);
        nextbuf = 1;
    }
    CP_COMMIT();

#pragma unroll 1
    for (int t = t0; t < t1; t++) {
        int nbi = bi, nbj = bj + 1;
        if (nbj == NTILE) { nbi = bi + 1; nbj = nbi; }
        bool diag = (bi == bj);

        CP_WAIT0();
        __syncthreads();

        bool canPre = (t + 1 < t1) && (nbi == bi);
        if (canPre) {
            fill_async(smb + (nextbuf ? P_B1 : P_B0),
                       g_X + (size_t)nbj * 128 * NDIM, tid);
            CP_COMMIT();
        }

        tile_compute(sm, diag ? P_A : (curbuf ? P_B1 : P_B0), bi, bj, diag, tid);

        if (canPre) { curbuf = nextbuf; nextbuf ^= 1; }
        bi = nbi; bj = nbj;
        if (t + 1 < t1 && !canPre) {
            __syncthreads();
            fill_async(smb + P_A, g_X + (size_t)bi * 128 * NDIM, tid);
            CP_COMMIT();
        }
    }
}

// ---------------------------------------------------------------------------
// K3: pointwise loss finish.
// ---------------------------------------------------------------------------
__global__ void __launch_bounds__(256) k_loss_fin(const float* __restrict__ pij,
                                                  float* __restrict__ out) {
    int el = blockIdx.x * 256 + threadIdx.x;
    if (el < NBATCH) {
        float den = (float)NDIM + g_den[el];
        float p = pij[el];
        out[el] = p * (logf(p) + logf(den) + logf((float)g_part));
    }
}

extern "C" void kernel_launch(void* const* d_in, const int* in_sizes, int n_in,
                              void* d_out, int out_size) {
    const float* pij        = (const float*)d_in[0];
    const float* noise_full = (const float*)d_in[1];
    const float* noise_i    = (const float*)d_in[2];
    const float* noise_j    = (const float*)d_in[3];
    const float* logits     = (const float*)d_in[4];
    const float* W          = (const float*)d_in[5];
    const int*   iv         = (const int*)d_in[7];
    const int*   jv         = (const int*)d_in[8];
    float* out = (float*)d_out;

    cudaFuncSetAttribute(k_gemm, cudaFuncAttributeMaxDynamicSharedMemorySize, SMEM_G);
    cudaFuncSetAttribute(k_pairwise, cudaFuncAttributeMaxDynamicSharedMemorySize, SMEM_PW);

    k_z<<<NROWS / 8, 256>>>(logits, noise_full, noise_i, noise_j, iv, jv);
    k_gemm<<<NROWS / 64, 256, SMEM_G>>>(W);
    k_pairwise<<<NPCTA, 256, SMEM_PW>>>();
    k_loss_fin<<<NBATCH / 256, 256>>>(pij, out);
}